// round 1
// baseline (speedup 1.0000x reference)
#include <cuda_runtime.h>
#include <math.h>

#define NTOK 4096
#define EMB 1024
#define FFD 4096
#define SEQ 2048

// ---------------- scratch (device globals: no runtime allocation) ----------
__device__ float g_ln1[NTOK * EMB];
__device__ float g_q[NTOK * EMB];
__device__ float g_k[NTOK * EMB];
__device__ float g_v[NTOK * EMB];
__device__ float g_attn[NTOK * EMB];
__device__ float g_x1[NTOK * EMB];
__device__ float g_ln2[NTOK * EMB];
__device__ float g_ff[NTOK * FFD];

// ---------------- layernorm: one block per row ------------------------------
__global__ __launch_bounds__(256) void ln_kernel(
    const float* __restrict__ x, const float* __restrict__ g,
    const float* __restrict__ b, float* __restrict__ out)
{
    int row = blockIdx.x;
    const float4* xr = (const float4*)(x + (size_t)row * EMB);
    float4 v = xr[threadIdx.x];                 // 256 * 4 = 1024
    float s  = v.x + v.y + v.z + v.w;
    float ss = v.x * v.x + v.y * v.y + v.z * v.z + v.w * v.w;
    #pragma unroll
    for (int o = 16; o; o >>= 1) {
        s  += __shfl_xor_sync(0xFFFFFFFFu, s,  o);
        ss += __shfl_xor_sync(0xFFFFFFFFu, ss, o);
    }
    __shared__ float sbuf[8], ssbuf[8];
    int w = threadIdx.x >> 5, l = threadIdx.x & 31;
    if (l == 0) { sbuf[w] = s; ssbuf[w] = ss; }
    __syncthreads();
    if (w == 0) {
        float s2  = (l < 8) ? sbuf[l]  : 0.f;
        float ss2 = (l < 8) ? ssbuf[l] : 0.f;
        #pragma unroll
        for (int o = 4; o; o >>= 1) {
            s2  += __shfl_xor_sync(0xFFFFFFFFu, s2,  o);
            ss2 += __shfl_xor_sync(0xFFFFFFFFu, ss2, o);
        }
        if (l == 0) { sbuf[0] = s2 * (1.f / EMB); ssbuf[0] = ss2 * (1.f / EMB); }
    }
    __syncthreads();
    float mean = sbuf[0];
    float var  = ssbuf[0] - mean * mean;
    float r    = rsqrtf(var + 1e-5f);
    float4 gg = ((const float4*)g)[threadIdx.x];
    float4 bb = ((const float4*)b)[threadIdx.x];
    float4 o4;
    o4.x = (v.x - mean) * r * gg.x + bb.x;
    o4.y = (v.y - mean) * r * gg.y + bb.y;
    o4.z = (v.z - mean) * r * gg.z + bb.z;
    o4.w = (v.w - mean) * r * gg.w + bb.w;
    ((float4*)(out + (size_t)row * EMB))[threadIdx.x] = o4;
}

// ---------------- GEMM: C = A[MxK] @ B[KxN] + bias, epilogue per MODE -------
// MODE 0: plain   MODE 1: tanh-GELU   MODE 2: + residual R
template <int MODE>
__global__ __launch_bounds__(256) void gemm_kernel(
    const float* __restrict__ A, const float* __restrict__ B,
    const float* __restrict__ bias, const float* __restrict__ R,
    float* __restrict__ C, int M, int N, int K)
{
    __shared__ float As[8][132];
    __shared__ float Bs[8][132];
    int tid = threadIdx.x;
    int tx = tid & 15, ty = tid >> 4;
    int m0 = blockIdx.y * 128, n0 = blockIdx.x * 128;

    float acc[8][8] = {};

    int am = tid >> 1, ak = (tid & 1) * 4;      // A tile: one float4 per thread
    int bk = tid >> 5, bn = (tid & 31) * 4;     // B tile: one float4 per thread
    const float* Aptr = A + (size_t)(m0 + am) * K + ak;
    const float* Bptr = B + (size_t)bk * N + n0 + bn;

    for (int k0 = 0; k0 < K; k0 += 8) {
        float4 a = *(const float4*)(Aptr + k0);
        float4 b = *(const float4*)(Bptr + (size_t)k0 * N);
        As[ak + 0][am] = a.x; As[ak + 1][am] = a.y;
        As[ak + 2][am] = a.z; As[ak + 3][am] = a.w;
        *(float4*)&Bs[bk][bn] = b;
        __syncthreads();
        #pragma unroll
        for (int kk = 0; kk < 8; kk++) {
            float ar[8], br[8];
            *(float4*)(ar)     = *(const float4*)&As[kk][ty * 8];
            *(float4*)(ar + 4) = *(const float4*)&As[kk][ty * 8 + 4];
            *(float4*)(br)     = *(const float4*)&Bs[kk][tx * 8];
            *(float4*)(br + 4) = *(const float4*)&Bs[kk][tx * 8 + 4];
            #pragma unroll
            for (int i = 0; i < 8; i++)
                #pragma unroll
                for (int j = 0; j < 8; j++)
                    acc[i][j] += ar[i] * br[j];
        }
        __syncthreads();
    }

    #pragma unroll
    for (int i = 0; i < 8; i++) {
        size_t row = (size_t)(m0 + ty * 8 + i);
        #pragma unroll
        for (int j = 0; j < 8; j++) {
            int col = n0 + tx * 8 + j;
            float c = acc[i][j] + bias[col];
            if (MODE == 1) {
                float xv = c;
                c = 0.5f * xv * (1.0f + tanhf(0.7978845608028654f *
                        (xv + 0.044715f * xv * xv * xv)));
            } else if (MODE == 2) {
                c += R[row * N + col];
            }
            C[row * N + col] = c;
        }
    }
}

// ---------------- flash attention: 1 thread / query row ---------------------
// grid (32 q-tiles, 16 heads, 2 batch), 64 threads. d=64 in registers.
__global__ __launch_bounds__(64) void attn_kernel(
    const float* __restrict__ Q, const float* __restrict__ K,
    const float* __restrict__ V, float* __restrict__ O)
{
    __shared__ float Ks[32][68];
    __shared__ float Vs[32][68];
    int qt = blockIdx.x, h = blockIdx.y, b = blockIdx.z;
    int t = threadIdx.x;

    size_t qbase = ((size_t)(b * SEQ + qt * 64 + t)) * EMB + h * 64;
    float4 q4[16];
    #pragma unroll
    for (int i = 0; i < 16; i++) q4[i] = *(const float4*)(Q + qbase + i * 4);

    float4 acc4[16];
    #pragma unroll
    for (int i = 0; i < 16; i++) acc4[i] = make_float4(0.f, 0.f, 0.f, 0.f);
    float m = -1e30f, l = 0.f;

    size_t kvbase = ((size_t)(b * SEQ)) * EMB + h * 64;

    for (int kt = 0; kt < SEQ; kt += 32) {
        // cooperative load of K/V tiles (32 rows x 64 cols), coalesced
        for (int i = t; i < 512; i += 64) {
            int r = i >> 4, c = (i & 15) << 2;
            size_t src = kvbase + (size_t)(kt + r) * EMB + c;
            *(float4*)&Ks[r][c] = *(const float4*)(K + src);
            *(float4*)&Vs[r][c] = *(const float4*)(V + src);
        }
        __syncthreads();

        float s[32];
        float mt = -1e30f;
        for (int j = 0; j < 32; j++) {
            const float4* kr = (const float4*)&Ks[j][0];
            float d0 = 0.f, d1 = 0.f, d2 = 0.f, d3 = 0.f;
            #pragma unroll
            for (int i = 0; i < 16; i += 4) {
                float4 k0 = kr[i], k1 = kr[i + 1], k2 = kr[i + 2], k3 = kr[i + 3];
                d0 += q4[i].x     * k0.x + q4[i].y     * k0.y + q4[i].z     * k0.z + q4[i].w     * k0.w;
                d1 += q4[i + 1].x * k1.x + q4[i + 1].y * k1.y + q4[i + 1].z * k1.z + q4[i + 1].w * k1.w;
                d2 += q4[i + 2].x * k2.x + q4[i + 2].y * k2.y + q4[i + 2].z * k2.z + q4[i + 2].w * k2.w;
                d3 += q4[i + 3].x * k3.x + q4[i + 3].y * k3.y + q4[i + 3].z * k3.z + q4[i + 3].w * k3.w;
            }
            float sj = (d0 + d1 + d2 + d3) * 0.125f;   // 1/sqrt(64)
            s[j] = sj;
            mt = fmaxf(mt, sj);
        }

        float mnew  = fmaxf(m, mt);
        float alpha = __expf(m - mnew);
        l *= alpha;
        #pragma unroll
        for (int i = 0; i < 16; i++) {
            acc4[i].x *= alpha; acc4[i].y *= alpha;
            acc4[i].z *= alpha; acc4[i].w *= alpha;
        }
        for (int j = 0; j < 32; j++) {
            float p = __expf(s[j] - mnew);
            l += p;
            const float4* vr = (const float4*)&Vs[j][0];
            #pragma unroll
            for (int i = 0; i < 16; i++) {
                float4 vv = vr[i];
                acc4[i].x += p * vv.x; acc4[i].y += p * vv.y;
                acc4[i].z += p * vv.z; acc4[i].w += p * vv.w;
            }
        }
        m = mnew;
        __syncthreads();
    }

    float inv = 1.f / l;
    #pragma unroll
    for (int i = 0; i < 16; i++) {
        float4 o;
        o.x = acc4[i].x * inv; o.y = acc4[i].y * inv;
        o.z = acc4[i].z * inv; o.w = acc4[i].w * inv;
        *(float4*)(O + qbase + i * 4) = o;
    }
}

// ---------------- launch ----------------------------------------------------
extern "C" void kernel_launch(void* const* d_in, const int* in_sizes, int n_in,
                              void* d_out, int out_size)
{
    const float* x     = (const float*)d_in[0];
    const float* Wq    = (const float*)d_in[1];
    const float* bq    = (const float*)d_in[2];
    const float* Wk    = (const float*)d_in[3];
    const float* bk    = (const float*)d_in[4];
    const float* Wv    = (const float*)d_in[5];
    const float* bv    = (const float*)d_in[6];
    const float* Wo    = (const float*)d_in[7];
    const float* bo    = (const float*)d_in[8];
    const float* W1    = (const float*)d_in[9];
    const float* b1    = (const float*)d_in[10];
    const float* W2    = (const float*)d_in[11];
    const float* b2    = (const float*)d_in[12];
    const float* ln1_g = (const float*)d_in[13];
    const float* ln1_b = (const float*)d_in[14];
    const float* ln2_g = (const float*)d_in[15];
    const float* ln2_b = (const float*)d_in[16];

    float *ln1, *q, *k, *v, *attn, *x1, *ln2, *ff;
    cudaGetSymbolAddress((void**)&ln1,  g_ln1);
    cudaGetSymbolAddress((void**)&q,    g_q);
    cudaGetSymbolAddress((void**)&k,    g_k);
    cudaGetSymbolAddress((void**)&v,    g_v);
    cudaGetSymbolAddress((void**)&attn, g_attn);
    cudaGetSymbolAddress((void**)&x1,   g_x1);
    cudaGetSymbolAddress((void**)&ln2,  g_ln2);
    cudaGetSymbolAddress((void**)&ff,   g_ff);

    dim3 gEE(EMB / 128, NTOK / 128);   // (8, 32)
    dim3 gEF(FFD / 128, NTOK / 128);   // (32, 32)

    // ln1 = LN(x)
    ln_kernel<<<NTOK, 256>>>(x, ln1_g, ln1_b, ln1);
    // q/k/v = ln1 @ W{q,k,v} + b
    gemm_kernel<0><<<gEE, 256>>>(ln1, Wq, bq, nullptr, q, NTOK, EMB, EMB);
    gemm_kernel<0><<<gEE, 256>>>(ln1, Wk, bk, nullptr, k, NTOK, EMB, EMB);
    gemm_kernel<0><<<gEE, 256>>>(ln1, Wv, bv, nullptr, v, NTOK, EMB, EMB);
    // attention
    attn_kernel<<<dim3(SEQ / 64, 16, 2), 64>>>(q, k, v, attn);
    // x1 = x + attn @ Wo + bo
    gemm_kernel<2><<<gEE, 256>>>(attn, Wo, bo, x, x1, NTOK, EMB, EMB);
    // ln2
    ln_kernel<<<NTOK, 256>>>(x1, ln2_g, ln2_b, ln2);
    // ff = gelu(ln2 @ W1 + b1)
    gemm_kernel<1><<<gEF, 256>>>(ln2, W1, b1, nullptr, ff, NTOK, FFD, EMB);
    // out = x1 + ff @ W2 + b2
    gemm_kernel<2><<<gEE, 256>>>(ff, W2, b2, x1, (float*)d_out, NTOK, EMB, FFD);
}

// round 4
// speedup vs baseline: 1.7735x; 1.7735x over previous
#include <cuda_runtime.h>
#include <cstdint>
#include <math.h>

#define NTOK 4096
#define EMB 1024
#define FFD 4096
#define SEQ 2048

// ---------------- scratch (device globals: no runtime allocation) ----------
__device__ float g_ln1[NTOK * EMB];
__device__ float g_q[NTOK * EMB];
__device__ float g_k[NTOK * EMB];
__device__ float g_v[NTOK * EMB];
__device__ float g_attn[NTOK * EMB];
__device__ float g_x1[NTOK * EMB];
__device__ float g_ln2[NTOK * EMB];
__device__ float g_ff[NTOK * FFD];
__device__ float g_WqT[EMB * EMB];
__device__ float g_WkT[EMB * EMB];
__device__ float g_WvT[EMB * EMB];
__device__ float g_WoT[EMB * EMB];
__device__ float g_W1T[EMB * FFD];
__device__ float g_W2T[FFD * EMB];

// ---------------- small helpers --------------------------------------------
__device__ __forceinline__ uint32_t smem_u32(const void* p) {
    uint32_t a;
    asm("{ .reg .u64 t; cvta.to.shared.u64 t, %1; cvt.u32.u64 %0, t; }"
        : "=r"(a) : "l"(p));
    return a;
}
__device__ __forceinline__ float rnd_tf32(float x) {
    uint32_t u;
    asm("cvt.rna.tf32.f32 %0, %1;" : "=r"(u) : "f"(x));
    return __uint_as_float(u);
}
__device__ __forceinline__ void cp16(uint32_t dst, const void* src) {
    asm volatile("cp.async.cg.shared.global [%0], [%1], 16;"
                 :: "r"(dst), "l"(src) : "memory");
}

// f32x2 packed math (family-portable on sm_100+)
#define FMA2(d, a, b, c) asm("fma.rn.f32x2 %0, %1, %2, %3;" : "=l"(d) : "l"(a), "l"(b), "l"(c))
#define ADD2(d, a, b)    asm("add.rn.f32x2 %0, %1, %2;"     : "=l"(d) : "l"(a), "l"(b))
#define MUL2(d, a, b)    asm("mul.rn.f32x2 %0, %1, %2;"     : "=l"(d) : "l"(a), "l"(b))
#define PACK2(d, lo, hi) asm("mov.b64 %0, {%1, %2};" : "=l"(d) : "r"(__float_as_uint(lo)), "r"(__float_as_uint(hi)))

typedef unsigned long long u64t;

// m16n8k8 tf32 mma (family-portable, sm_80+)
#define MMA_TF32(d, a, b)                                                     \
    asm volatile("mma.sync.aligned.m16n8k8.row.col.f32.tf32.tf32.f32 "        \
        "{%0,%1,%2,%3}, {%4,%5,%6,%7}, {%8,%9}, {%0,%1,%2,%3};"               \
        : "+f"((d)[0]), "+f"((d)[1]), "+f"((d)[2]), "+f"((d)[3])              \
        : "r"((a)[0]), "r"((a)[1]), "r"((a)[2]), "r"((a)[3]),                 \
          "r"((b)[0]), "r"((b)[1]))

#define PADF 36                       // floats per smem row (bank-conflict-free)
#define TILEF (128 * PADF)            // 4608 floats = 18432 B per tile
#define BUFF  (2 * TILEF)             // A tile + B tile per buffer
#define GSMEM_BYTES (2 * BUFF * 4)    // 73728 B

// ---------------- tensor-core GEMM: C = A[M,K] @ Bt[N,K]^T + bias ----------
// MODE 0: plain  MODE 1: tanh-GELU + tf32 round  MODE 2: + residual R
template <int MODE>
__global__ __launch_bounds__(256) void gemm_mma(
    const float* __restrict__ A, const float* __restrict__ Bt,
    const float* __restrict__ bias, const float* __restrict__ R,
    float* __restrict__ C, int M, int N, int K)
{
    extern __shared__ float smem[];
    uint32_t sb = smem_u32(smem);

    int tid = threadIdx.x, wid = tid >> 5, lane = tid & 31;
    int tr = lane >> 2, tc = lane & 3;
    int wm0 = (wid >> 1) * 32, wn0 = (wid & 1) * 64;
    int m0 = blockIdx.y * 128, n0 = blockIdx.x * 128;

    float acc[2][8][4];
    #pragma unroll
    for (int i = 0; i < 2; i++)
        #pragma unroll
        for (int j = 0; j < 8; j++)
            #pragma unroll
            for (int r = 0; r < 4; r++) acc[i][j][r] = 0.f;

    const int NC = K >> 5;

    auto load_chunk = [&](int c, int s) {
        uint32_t ab = sb + s * (BUFF * 4);
        uint32_t bb = ab + TILEF * 4;
        const float* Ap = A + (size_t)m0 * K + (c << 5);
        const float* Bp = Bt + (size_t)n0 * K + (c << 5);
        #pragma unroll
        for (int i = 0; i < 4; i++) {
            int gid = (i << 8) + tid;          // 0..1023
            int row = gid >> 3, g = gid & 7;   // 128 rows x 8 16B-groups
            uint32_t doff = (uint32_t)row * (PADF * 4) + (uint32_t)g * 16;
            cp16(ab + doff, Ap + (size_t)row * K + g * 4);
            cp16(bb + doff, Bp + (size_t)row * K + g * 4);
        }
        asm volatile("cp.async.commit_group;" ::: "memory");
    };

    load_chunk(0, 0);
    for (int c = 0; c < NC; c++) {
        if (c + 1 < NC) {
            load_chunk(c + 1, (c + 1) & 1);
            asm volatile("cp.async.wait_group 1;" ::: "memory");
        } else {
            asm volatile("cp.async.wait_group 0;" ::: "memory");
        }
        __syncthreads();

        const float* Af = smem + (c & 1) * BUFF;
        const float* Bf = Af + TILEF;
        #pragma unroll
        for (int k8 = 0; k8 < 4; k8++) {
            int k0 = k8 << 3;
            uint32_t a[2][4];
            #pragma unroll
            for (int mf = 0; mf < 2; mf++) {
                int r = wm0 + mf * 16 + tr;
                a[mf][0] = __float_as_uint(Af[r * PADF + k0 + tc]);
                a[mf][1] = __float_as_uint(Af[(r + 8) * PADF + k0 + tc]);
                a[mf][2] = __float_as_uint(Af[r * PADF + k0 + 4 + tc]);
                a[mf][3] = __float_as_uint(Af[(r + 8) * PADF + k0 + 4 + tc]);
            }
            uint32_t b[8][2];
            #pragma unroll
            for (int nf = 0; nf < 8; nf++) {
                int r = wn0 + nf * 8 + tr;
                b[nf][0] = __float_as_uint(Bf[r * PADF + k0 + tc]);
                b[nf][1] = __float_as_uint(Bf[r * PADF + k0 + 4 + tc]);
            }
            #pragma unroll
            for (int mf = 0; mf < 2; mf++)
                #pragma unroll
                for (int nf = 0; nf < 8; nf++)
                    MMA_TF32(acc[mf][nf], a[mf], b[nf]);
        }
        __syncthreads();
    }

    // epilogue
    #pragma unroll
    for (int mf = 0; mf < 2; mf++) {
        int rbase = m0 + wm0 + mf * 16 + tr;
        #pragma unroll
        for (int nf = 0; nf < 8; nf++) {
            int col = n0 + wn0 + nf * 8 + tc * 2;
            float b0 = bias[col], b1 = bias[col + 1];
            float v0 = acc[mf][nf][0] + b0;
            float v1 = acc[mf][nf][1] + b1;
            float v2 = acc[mf][nf][2] + b0;
            float v3 = acc[mf][nf][3] + b1;
            if (MODE == 1) {
                #define GELU(v) (0.5f * (v) * (1.0f + tanhf(0.7978845608028654f * ((v) + 0.044715f * (v) * (v) * (v)))))
                v0 = rnd_tf32(GELU(v0)); v1 = rnd_tf32(GELU(v1));
                v2 = rnd_tf32(GELU(v2)); v3 = rnd_tf32(GELU(v3));
                #undef GELU
            } else if (MODE == 2) {
                float2 r0 = *(const float2*)(R + (size_t)rbase * N + col);
                float2 r1 = *(const float2*)(R + (size_t)(rbase + 8) * N + col);
                v0 += r0.x; v1 += r0.y; v2 += r1.x; v3 += r1.y;
            }
            *(float2*)(C + (size_t)rbase * N + col) = make_float2(v0, v1);
            *(float2*)(C + (size_t)(rbase + 8) * N + col) = make_float2(v2, v3);
        }
    }
}

// ---------------- weight transpose + tf32 round: W[K,N] -> Wt[N,K] ---------
__global__ __launch_bounds__(256) void transpose_rnd(
    const float* __restrict__ W, float* __restrict__ Wt, int K, int N)
{
    __shared__ float t[32][33];
    int bx = blockIdx.x * 32, by = blockIdx.y * 32;
    int x = threadIdx.x, y = threadIdx.y;
    #pragma unroll
    for (int r = 0; r < 32; r += 8)
        t[y + r][x] = W[(size_t)(by + y + r) * N + bx + x];
    __syncthreads();
    #pragma unroll
    for (int r = 0; r < 32; r += 8)
        Wt[(size_t)(bx + y + r) * K + by + x] = rnd_tf32(t[x][y + r]);
}

// ---------------- layernorm (output rounded to tf32: feeds GEMM A only) ----
__global__ __launch_bounds__(256) void ln_kernel(
    const float* __restrict__ x, const float* __restrict__ g,
    const float* __restrict__ b, float* __restrict__ out)
{
    int row = blockIdx.x;
    const float4* xr = (const float4*)(x + (size_t)row * EMB);
    float4 v = xr[threadIdx.x];
    float s  = v.x + v.y + v.z + v.w;
    float ss = v.x * v.x + v.y * v.y + v.z * v.z + v.w * v.w;
    #pragma unroll
    for (int o = 16; o; o >>= 1) {
        s  += __shfl_xor_sync(0xFFFFFFFFu, s,  o);
        ss += __shfl_xor_sync(0xFFFFFFFFu, ss, o);
    }
    __shared__ float sbuf[8], ssbuf[8];
    int w = threadIdx.x >> 5, l = threadIdx.x & 31;
    if (l == 0) { sbuf[w] = s; ssbuf[w] = ss; }
    __syncthreads();
    if (w == 0) {
        float s2  = (l < 8) ? sbuf[l]  : 0.f;
        float ss2 = (l < 8) ? ssbuf[l] : 0.f;
        #pragma unroll
        for (int o = 4; o; o >>= 1) {
            s2  += __shfl_xor_sync(0xFFFFFFFFu, s2,  o);
            ss2 += __shfl_xor_sync(0xFFFFFFFFu, ss2, o);
        }
        if (l == 0) { sbuf[0] = s2 * (1.f / EMB); ssbuf[0] = ss2 * (1.f / EMB); }
    }
    __syncthreads();
    float mean = sbuf[0];
    float var  = ssbuf[0] - mean * mean;
    float r    = rsqrtf(var + 1e-5f);
    float4 gg = ((const float4*)g)[threadIdx.x];
    float4 bb = ((const float4*)b)[threadIdx.x];
    float4 o4;
    o4.x = rnd_tf32((v.x - mean) * r * gg.x + bb.x);
    o4.y = rnd_tf32((v.y - mean) * r * gg.y + bb.y);
    o4.z = rnd_tf32((v.z - mean) * r * gg.z + bb.z);
    o4.w = rnd_tf32((v.w - mean) * r * gg.w + bb.w);
    ((float4*)(out + (size_t)row * EMB))[threadIdx.x] = o4;
}

// ---------------- flash attention, f32x2 packed math ------------------------
__global__ __launch_bounds__(64) void attn_kernel(
    const float* __restrict__ Q, const float* __restrict__ K,
    const float* __restrict__ V, float* __restrict__ O)
{
    __shared__ float Ks[32][68];
    __shared__ float Vs[32][68];
    int qt = blockIdx.x, h = blockIdx.y, b = blockIdx.z;
    int t = threadIdx.x;

    size_t qbase = ((size_t)(b * SEQ + qt * 64 + t)) * EMB + h * 64;
    u64t qp[32];
    #pragma unroll
    for (int i = 0; i < 32; i++) qp[i] = *(const u64t*)(Q + qbase + 2 * i);

    u64t acc[32];
    #pragma unroll
    for (int i = 0; i < 32; i++) acc[i] = 0ull;
    float m = -1e30f, l = 0.f;

    size_t kvbase = ((size_t)(b * SEQ)) * EMB + h * 64;

    for (int kt = 0; kt < SEQ; kt += 32) {
        for (int i = t; i < 512; i += 64) {
            int r = i >> 4, c = (i & 15) << 2;
            size_t src = kvbase + (size_t)(kt + r) * EMB + c;
            *(float4*)&Ks[r][c] = *(const float4*)(K + src);
            *(float4*)&Vs[r][c] = *(const float4*)(V + src);
        }
        __syncthreads();

        float s[32];
        float mt = -1e30f;
        #pragma unroll 4
        for (int j = 0; j < 32; j++) {
            const u64t* kr = (const u64t*)&Ks[j][0];
            u64t d0 = 0ull, d1 = 0ull, d2 = 0ull, d3 = 0ull;
            #pragma unroll
            for (int i = 0; i < 32; i += 4) {
                FMA2(d0, qp[i + 0], kr[i + 0], d0);
                FMA2(d1, qp[i + 1], kr[i + 1], d1);
                FMA2(d2, qp[i + 2], kr[i + 2], d2);
                FMA2(d3, qp[i + 3], kr[i + 3], d3);
            }
            ADD2(d0, d0, d1); ADD2(d2, d2, d3); ADD2(d0, d0, d2);
            float lo = __uint_as_float((uint32_t)d0);
            float hi = __uint_as_float((uint32_t)(d0 >> 32));
            float sj = (lo + hi) * 0.125f;
            s[j] = sj;
            mt = fmaxf(mt, sj);
        }

        float mnew  = fmaxf(m, mt);
        float alpha = __expf(m - mnew);
        l *= alpha;
        u64t ap; PACK2(ap, alpha, alpha);
        #pragma unroll
        for (int i = 0; i < 32; i++) MUL2(acc[i], acc[i], ap);

        #pragma unroll 2
        for (int j = 0; j < 32; j++) {
            float p = __expf(s[j] - mnew);
            l += p;
            u64t pp; PACK2(pp, p, p);
            const u64t* vr = (const u64t*)&Vs[j][0];
            #pragma unroll
            for (int i = 0; i < 32; i++)
                FMA2(acc[i], pp, vr[i], acc[i]);
        }
        m = mnew;
        __syncthreads();
    }

    float inv = 1.f / l;
    u64t ip; PACK2(ip, inv, inv);
    #pragma unroll
    for (int i = 0; i < 32; i++) {
        MUL2(acc[i], acc[i], ip);
        float2 o;
        o.x = rnd_tf32(__uint_as_float((uint32_t)acc[i]));   // feeds Wo GEMM (tf32 A)
        o.y = rnd_tf32(__uint_as_float((uint32_t)(acc[i] >> 32)));
        *(float2*)(O + qbase + 2 * i) = o;
    }
}

// ---------------- launch ----------------------------------------------------
extern "C" void kernel_launch(void* const* d_in, const int* in_sizes, int n_in,
                              void* d_out, int out_size)
{
    const float* x     = (const float*)d_in[0];
    const float* Wq    = (const float*)d_in[1];
    const float* bq    = (const float*)d_in[2];
    const float* Wk    = (const float*)d_in[3];
    const float* bk    = (const float*)d_in[4];
    const float* Wv    = (const float*)d_in[5];
    const float* bv    = (const float*)d_in[6];
    const float* Wo    = (const float*)d_in[7];
    const float* bo    = (const float*)d_in[8];
    const float* W1    = (const float*)d_in[9];
    const float* b1    = (const float*)d_in[10];
    const float* W2    = (const float*)d_in[11];
    const float* b2    = (const float*)d_in[12];
    const float* ln1_g = (const float*)d_in[13];
    const float* ln1_b = (const float*)d_in[14];
    const float* ln2_g = (const float*)d_in[15];
    const float* ln2_b = (const float*)d_in[16];

    float *ln1, *q, *k, *v, *attn, *x1, *ln2, *ff;
    float *WqT, *WkT, *WvT, *WoT, *W1T, *W2T;
    cudaGetSymbolAddress((void**)&ln1,  g_ln1);
    cudaGetSymbolAddress((void**)&q,    g_q);
    cudaGetSymbolAddress((void**)&k,    g_k);
    cudaGetSymbolAddress((void**)&v,    g_v);
    cudaGetSymbolAddress((void**)&attn, g_attn);
    cudaGetSymbolAddress((void**)&x1,   g_x1);
    cudaGetSymbolAddress((void**)&ln2,  g_ln2);
    cudaGetSymbolAddress((void**)&ff,   g_ff);
    cudaGetSymbolAddress((void**)&WqT,  g_WqT);
    cudaGetSymbolAddress((void**)&WkT,  g_WkT);
    cudaGetSymbolAddress((void**)&WvT,  g_WvT);
    cudaGetSymbolAddress((void**)&WoT,  g_WoT);
    cudaGetSymbolAddress((void**)&W1T,  g_W1T);
    cudaGetSymbolAddress((void**)&W2T,  g_W2T);

    cudaFuncSetAttribute(gemm_mma<0>, cudaFuncAttributeMaxDynamicSharedMemorySize, GSMEM_BYTES);
    cudaFuncSetAttribute(gemm_mma<1>, cudaFuncAttributeMaxDynamicSharedMemorySize, GSMEM_BYTES);
    cudaFuncSetAttribute(gemm_mma<2>, cudaFuncAttributeMaxDynamicSharedMemorySize, GSMEM_BYTES);

    dim3 tb(32, 8);
    transpose_rnd<<<dim3(EMB / 32, EMB / 32), tb>>>(Wq, WqT, EMB, EMB);
    transpose_rnd<<<dim3(EMB / 32, EMB / 32), tb>>>(Wk, WkT, EMB, EMB);
    transpose_rnd<<<dim3(EMB / 32, EMB / 32), tb>>>(Wv, WvT, EMB, EMB);
    transpose_rnd<<<dim3(EMB / 32, EMB / 32), tb>>>(Wo, WoT, EMB, EMB);
    transpose_rnd<<<dim3(FFD / 32, EMB / 32), tb>>>(W1, W1T, EMB, FFD);
    transpose_rnd<<<dim3(EMB / 32, FFD / 32), tb>>>(W2, W2T, FFD, EMB);

    dim3 gEE(EMB / 128, NTOK / 128);   // (8, 32)
    dim3 gEF(FFD / 128, NTOK / 128);   // (32, 32)

    ln_kernel<<<NTOK, 256>>>(x, ln1_g, ln1_b, ln1);
    gemm_mma<0><<<gEE, 256, GSMEM_BYTES>>>(ln1, WqT, bq, nullptr, q, NTOK, EMB, EMB);
    gemm_mma<0><<<gEE, 256, GSMEM_BYTES>>>(ln1, WkT, bk, nullptr, k, NTOK, EMB, EMB);
    gemm_mma<0><<<gEE, 256, GSMEM_BYTES>>>(ln1, WvT, bv, nullptr, v, NTOK, EMB, EMB);
    attn_kernel<<<dim3(SEQ / 64, 16, 2), 64>>>(q, k, v, attn);
    gemm_mma<2><<<gEE, 256, GSMEM_BYTES>>>(attn, WoT, bo, x, x1, NTOK, EMB, EMB);
    ln_kernel<<<NTOK, 256>>>(x1, ln2_g, ln2_b, ln2);
    gemm_mma<1><<<gEF, 256, GSMEM_BYTES>>>(ln2, W1T, b1, nullptr, ff, NTOK, FFD, EMB);
    gemm_mma<2><<<gEE, 256, GSMEM_BYTES>>>(ff, W2T, b2, x1, (float*)d_out, NTOK, EMB, FFD);
}

// round 5
// speedup vs baseline: 3.6062x; 2.0334x over previous
#include <cuda_runtime.h>
#include <cstdint>
#include <math.h>

#define NTOK 4096
#define EMB 1024
#define FFD 4096
#define SEQ 2048

// ---------------- scratch (device globals: no runtime allocation) ----------
__device__ float g_ln1[NTOK * EMB];
__device__ float g_q[NTOK * EMB];
__device__ float g_k[NTOK * EMB];
__device__ float g_v[NTOK * EMB];
__device__ float g_attn[NTOK * EMB];
__device__ float g_x1[NTOK * EMB];
__device__ float g_ln2[NTOK * EMB];
__device__ float g_ff[NTOK * FFD];
__device__ float g_WqT[EMB * EMB];
__device__ float g_WkT[EMB * EMB];
__device__ float g_WvT[EMB * EMB];
__device__ float g_WoT[EMB * EMB];
__device__ float g_W1T[EMB * FFD];
__device__ float g_W2T[FFD * EMB];

// ---------------- small helpers --------------------------------------------
__device__ __forceinline__ uint32_t smem_u32(const void* p) {
    uint32_t a;
    asm("{ .reg .u64 t; cvta.to.shared.u64 t, %1; cvt.u32.u64 %0, t; }"
        : "=r"(a) : "l"(p));
    return a;
}
__device__ __forceinline__ float rnd_tf32(float x) {
    uint32_t u;
    asm("cvt.rna.tf32.f32 %0, %1;" : "=r"(u) : "f"(x));
    return __uint_as_float(u);
}
__device__ __forceinline__ void cp16(uint32_t dst, const void* src) {
    asm volatile("cp.async.cg.shared.global [%0], [%1], 16;"
                 :: "r"(dst), "l"(src) : "memory");
}

// m16n8k8 tf32 mma (family-portable, sm_80+)
#define MMA_TF32(d, a, b)                                                     \
    asm volatile("mma.sync.aligned.m16n8k8.row.col.f32.tf32.tf32.f32 "        \
        "{%0,%1,%2,%3}, {%4,%5,%6,%7}, {%8,%9}, {%0,%1,%2,%3};"               \
        : "+f"((d)[0]), "+f"((d)[1]), "+f"((d)[2]), "+f"((d)[3])              \
        : "r"((a)[0]), "r"((a)[1]), "r"((a)[2]), "r"((a)[3]),                 \
          "r"((b)[0]), "r"((b)[1]))

#define PADF 36                       // gemm smem row pitch (floats)
#define TILEF (128 * PADF)
#define BUFF  (2 * TILEF)
#define GSMEM_BYTES (2 * BUFF * 4)

// ---------------- tensor-core GEMM: C = A[M,K] @ Bt[N,K]^T + bias ----------
// MODE 0: plain  MODE 1: tanh-GELU + tf32 round  MODE 2: + residual R
template <int MODE>
__global__ __launch_bounds__(256) void gemm_mma(
    const float* __restrict__ A, const float* __restrict__ Bt,
    const float* __restrict__ bias, const float* __restrict__ R,
    float* __restrict__ C, int M, int N, int K)
{
    extern __shared__ float smem[];
    uint32_t sb = smem_u32(smem);

    int tid = threadIdx.x, wid = tid >> 5, lane = tid & 31;
    int tr = lane >> 2, tc = lane & 3;
    int wm0 = (wid >> 1) * 32, wn0 = (wid & 1) * 64;
    int m0 = blockIdx.y * 128, n0 = blockIdx.x * 128;

    float acc[2][8][4];
    #pragma unroll
    for (int i = 0; i < 2; i++)
        #pragma unroll
        for (int j = 0; j < 8; j++)
            #pragma unroll
            for (int r = 0; r < 4; r++) acc[i][j][r] = 0.f;

    const int NC = K >> 5;

    auto load_chunk = [&](int c, int s) {
        uint32_t ab = sb + s * (BUFF * 4);
        uint32_t bb = ab + TILEF * 4;
        const float* Ap = A + (size_t)m0 * K + (c << 5);
        const float* Bp = Bt + (size_t)n0 * K + (c << 5);
        #pragma unroll
        for (int i = 0; i < 4; i++) {
            int gid = (i << 8) + tid;
            int row = gid >> 3, g = gid & 7;
            uint32_t doff = (uint32_t)row * (PADF * 4) + (uint32_t)g * 16;
            cp16(ab + doff, Ap + (size_t)row * K + g * 4);
            cp16(bb + doff, Bp + (size_t)row * K + g * 4);
        }
        asm volatile("cp.async.commit_group;" ::: "memory");
    };

    load_chunk(0, 0);
    for (int c = 0; c < NC; c++) {
        if (c + 1 < NC) {
            load_chunk(c + 1, (c + 1) & 1);
            asm volatile("cp.async.wait_group 1;" ::: "memory");
        } else {
            asm volatile("cp.async.wait_group 0;" ::: "memory");
        }
        __syncthreads();

        const float* Af = smem + (c & 1) * BUFF;
        const float* Bf = Af + TILEF;
        #pragma unroll
        for (int k8 = 0; k8 < 4; k8++) {
            int k0 = k8 << 3;
            uint32_t a[2][4];
            #pragma unroll
            for (int mf = 0; mf < 2; mf++) {
                int r = wm0 + mf * 16 + tr;
                a[mf][0] = __float_as_uint(Af[r * PADF + k0 + tc]);
                a[mf][1] = __float_as_uint(Af[(r + 8) * PADF + k0 + tc]);
                a[mf][2] = __float_as_uint(Af[r * PADF + k0 + 4 + tc]);
                a[mf][3] = __float_as_uint(Af[(r + 8) * PADF + k0 + 4 + tc]);
            }
            uint32_t b[8][2];
            #pragma unroll
            for (int nf = 0; nf < 8; nf++) {
                int r = wn0 + nf * 8 + tr;
                b[nf][0] = __float_as_uint(Bf[r * PADF + k0 + tc]);
                b[nf][1] = __float_as_uint(Bf[r * PADF + k0 + 4 + tc]);
            }
            #pragma unroll
            for (int mf = 0; mf < 2; mf++)
                #pragma unroll
                for (int nf = 0; nf < 8; nf++)
                    MMA_TF32(acc[mf][nf], a[mf], b[nf]);
        }
        __syncthreads();
    }

    #pragma unroll
    for (int mf = 0; mf < 2; mf++) {
        int rbase = m0 + wm0 + mf * 16 + tr;
        #pragma unroll
        for (int nf = 0; nf < 8; nf++) {
            int col = n0 + wn0 + nf * 8 + tc * 2;
            float b0 = bias[col], b1 = bias[col + 1];
            float v0 = acc[mf][nf][0] + b0;
            float v1 = acc[mf][nf][1] + b1;
            float v2 = acc[mf][nf][2] + b0;
            float v3 = acc[mf][nf][3] + b1;
            if (MODE == 1) {
                #define GELU(v) (0.5f * (v) * (1.0f + tanhf(0.7978845608028654f * ((v) + 0.044715f * (v) * (v) * (v)))))
                v0 = rnd_tf32(GELU(v0)); v1 = rnd_tf32(GELU(v1));
                v2 = rnd_tf32(GELU(v2)); v3 = rnd_tf32(GELU(v3));
                #undef GELU
            } else if (MODE == 2) {
                float2 r0 = *(const float2*)(R + (size_t)rbase * N + col);
                float2 r1 = *(const float2*)(R + (size_t)(rbase + 8) * N + col);
                v0 += r0.x; v1 += r0.y; v2 += r1.x; v3 += r1.y;
            }
            *(float2*)(C + (size_t)rbase * N + col) = make_float2(v0, v1);
            *(float2*)(C + (size_t)(rbase + 8) * N + col) = make_float2(v2, v3);
        }
    }
}

// ---------------- weight transpose + tf32 round: W[K,N] -> Wt[N,K] ---------
__global__ __launch_bounds__(256) void transpose_rnd(
    const float* __restrict__ W, float* __restrict__ Wt, int K, int N)
{
    __shared__ float t[32][33];
    int bx = blockIdx.x * 32, by = blockIdx.y * 32;
    int x = threadIdx.x, y = threadIdx.y;
    #pragma unroll
    for (int r = 0; r < 32; r += 8)
        t[y + r][x] = W[(size_t)(by + y + r) * N + bx + x];
    __syncthreads();
    #pragma unroll
    for (int r = 0; r < 32; r += 8)
        Wt[(size_t)(bx + y + r) * K + by + x] = rnd_tf32(t[x][y + r]);
}

// ---------------- layernorm (output rounded to tf32: feeds GEMM A only) ----
__global__ __launch_bounds__(256) void ln_kernel(
    const float* __restrict__ x, const float* __restrict__ g,
    const float* __restrict__ b, float* __restrict__ out)
{
    int row = blockIdx.x;
    const float4* xr = (const float4*)(x + (size_t)row * EMB);
    float4 v = xr[threadIdx.x];
    float s  = v.x + v.y + v.z + v.w;
    float ss = v.x * v.x + v.y * v.y + v.z * v.z + v.w * v.w;
    #pragma unroll
    for (int o = 16; o; o >>= 1) {
        s  += __shfl_xor_sync(0xFFFFFFFFu, s,  o);
        ss += __shfl_xor_sync(0xFFFFFFFFu, ss, o);
    }
    __shared__ float sbuf[8], ssbuf[8];
    int w = threadIdx.x >> 5, l = threadIdx.x & 31;
    if (l == 0) { sbuf[w] = s; ssbuf[w] = ss; }
    __syncthreads();
    if (w == 0) {
        float s2  = (l < 8) ? sbuf[l]  : 0.f;
        float ss2 = (l < 8) ? ssbuf[l] : 0.f;
        #pragma unroll
        for (int o = 4; o; o >>= 1) {
            s2  += __shfl_xor_sync(0xFFFFFFFFu, s2,  o);
            ss2 += __shfl_xor_sync(0xFFFFFFFFu, ss2, o);
        }
        if (l == 0) { sbuf[0] = s2 * (1.f / EMB); ssbuf[0] = ss2 * (1.f / EMB); }
    }
    __syncthreads();
    float mean = sbuf[0];
    float var  = ssbuf[0] - mean * mean;
    float r    = rsqrtf(var + 1e-5f);
    float4 gg = ((const float4*)g)[threadIdx.x];
    float4 bb = ((const float4*)b)[threadIdx.x];
    float4 o4;
    o4.x = rnd_tf32((v.x - mean) * r * gg.x + bb.x);
    o4.y = rnd_tf32((v.y - mean) * r * gg.y + bb.y);
    o4.z = rnd_tf32((v.z - mean) * r * gg.z + bb.z);
    o4.w = rnd_tf32((v.w - mean) * r * gg.w + bb.w);
    ((float4*)(out + (size_t)row * EMB))[threadIdx.x] = o4;
}

// ---------------- flash attention on tf32 MMA -------------------------------
// CTA: 64 q-rows of one (b,h). 4 warps x 16 q-rows. K/V tiles of 64 keys.
#define APAD 76   // smem row pitch (floats): conflict-free frag patterns
__global__ __launch_bounds__(128) void attn_mma(
    const float* __restrict__ Q, const float* __restrict__ K,
    const float* __restrict__ V, float* __restrict__ O)
{
    __shared__ float Ks[64][APAD];
    __shared__ float Vs[64][APAD];
    __shared__ float QP[64][APAD];   // Q staging, then per-warp P slices

    int qt = blockIdx.x, h = blockIdx.y, b = blockIdx.z;
    int tid = threadIdx.x, wid = tid >> 5, lane = tid & 31;
    int tr = lane >> 2, tc = lane & 3;

    size_t qrow0 = (size_t)b * SEQ + qt * 64;

    // stage Q tile (64x64), tf32-rounded
    for (int i = tid; i < 64 * 16; i += 128) {
        int r = i >> 4, c4 = (i & 15) << 2;
        float4 v = *(const float4*)(Q + (qrow0 + r) * EMB + h * 64 + c4);
        float4 o;
        o.x = rnd_tf32(v.x); o.y = rnd_tf32(v.y);
        o.z = rnd_tf32(v.z); o.w = rnd_tf32(v.w);
        *(float4*)&QP[r][c4] = o;
    }
    __syncthreads();

    // Q fragments (register-resident for the whole loop)
    int qr = wid * 16;
    uint32_t qf[8][4];
    #pragma unroll
    for (int k8 = 0; k8 < 8; k8++) {
        int k0 = k8 << 3;
        qf[k8][0] = __float_as_uint(QP[qr + tr][k0 + tc]);
        qf[k8][1] = __float_as_uint(QP[qr + tr + 8][k0 + tc]);
        qf[k8][2] = __float_as_uint(QP[qr + tr][k0 + 4 + tc]);
        qf[k8][3] = __float_as_uint(QP[qr + tr + 8][k0 + 4 + tc]);
    }
    __syncthreads();   // QP now free for P

    float oacc[8][4];
    #pragma unroll
    for (int nf = 0; nf < 8; nf++)
        #pragma unroll
        for (int r = 0; r < 4; r++) oacc[nf][r] = 0.f;
    float m0 = -1e30f, m1 = -1e30f, l0 = 0.f, l1 = 0.f;

    size_t krow0 = (size_t)b * SEQ;
    for (int kt = 0; kt < SEQ / 64; kt++) {
        // load K/V tile (tf32-rounded)
        for (int i = tid; i < 64 * 16; i += 128) {
            int r = i >> 4, c4 = (i & 15) << 2;
            size_t src = (krow0 + kt * 64 + r) * EMB + h * 64 + c4;
            float4 kv = *(const float4*)(K + src);
            float4 ko;
            ko.x = rnd_tf32(kv.x); ko.y = rnd_tf32(kv.y);
            ko.z = rnd_tf32(kv.z); ko.w = rnd_tf32(kv.w);
            *(float4*)&Ks[r][c4] = ko;
            float4 vv = *(const float4*)(V + src);
            float4 vo;
            vo.x = rnd_tf32(vv.x); vo.y = rnd_tf32(vv.y);
            vo.z = rnd_tf32(vv.z); vo.w = rnd_tf32(vv.w);
            *(float4*)&Vs[r][c4] = vo;
        }
        __syncthreads();

        // S = Q @ K^T (scaled)
        float sacc[8][4];
        #pragma unroll
        for (int nf = 0; nf < 8; nf++)
            #pragma unroll
            for (int r = 0; r < 4; r++) sacc[nf][r] = 0.f;
        #pragma unroll
        for (int k8 = 0; k8 < 8; k8++) {
            int k0 = k8 << 3;
            #pragma unroll
            for (int nf = 0; nf < 8; nf++) {
                uint32_t bfr[2];
                bfr[0] = __float_as_uint(Ks[nf * 8 + tr][k0 + tc]);
                bfr[1] = __float_as_uint(Ks[nf * 8 + tr][k0 + 4 + tc]);
                MMA_TF32(sacc[nf], qf[k8], bfr);
            }
        }

        // online softmax (rows tr -> m0/l0, tr+8 -> m1/l1)
        float mt0 = -1e30f, mt1 = -1e30f;
        #pragma unroll
        for (int nf = 0; nf < 8; nf++) {
            sacc[nf][0] *= 0.125f; sacc[nf][1] *= 0.125f;
            sacc[nf][2] *= 0.125f; sacc[nf][3] *= 0.125f;
            mt0 = fmaxf(mt0, fmaxf(sacc[nf][0], sacc[nf][1]));
            mt1 = fmaxf(mt1, fmaxf(sacc[nf][2], sacc[nf][3]));
        }
        mt0 = fmaxf(mt0, __shfl_xor_sync(0xFFFFFFFFu, mt0, 1));
        mt0 = fmaxf(mt0, __shfl_xor_sync(0xFFFFFFFFu, mt0, 2));
        mt1 = fmaxf(mt1, __shfl_xor_sync(0xFFFFFFFFu, mt1, 1));
        mt1 = fmaxf(mt1, __shfl_xor_sync(0xFFFFFFFFu, mt1, 2));
        float mn0 = fmaxf(m0, mt0), mn1 = fmaxf(m1, mt1);
        float a0 = __expf(m0 - mn0), a1 = __expf(m1 - mn1);
        float rs0 = 0.f, rs1 = 0.f;
        #pragma unroll
        for (int nf = 0; nf < 8; nf++) {
            float p0 = __expf(sacc[nf][0] - mn0);
            float p1 = __expf(sacc[nf][1] - mn0);
            float p2 = __expf(sacc[nf][2] - mn1);
            float p3 = __expf(sacc[nf][3] - mn1);
            rs0 += p0 + p1; rs1 += p2 + p3;
            int col = nf * 8 + tc * 2;
            *(float2*)&QP[qr + tr][col]     = make_float2(rnd_tf32(p0), rnd_tf32(p1));
            *(float2*)&QP[qr + tr + 8][col] = make_float2(rnd_tf32(p2), rnd_tf32(p3));
        }
        rs0 += __shfl_xor_sync(0xFFFFFFFFu, rs0, 1);
        rs0 += __shfl_xor_sync(0xFFFFFFFFu, rs0, 2);
        rs1 += __shfl_xor_sync(0xFFFFFFFFu, rs1, 1);
        rs1 += __shfl_xor_sync(0xFFFFFFFFu, rs1, 2);
        l0 = l0 * a0 + rs0; l1 = l1 * a1 + rs1;
        m0 = mn0; m1 = mn1;
        #pragma unroll
        for (int nf = 0; nf < 8; nf++) {
            oacc[nf][0] *= a0; oacc[nf][1] *= a0;
            oacc[nf][2] *= a1; oacc[nf][3] *= a1;
        }
        __syncwarp();

        // O += P @ V
        #pragma unroll
        for (int k8 = 0; k8 < 8; k8++) {
            int k0 = k8 << 3;
            uint32_t pa[4];
            pa[0] = __float_as_uint(QP[qr + tr][k0 + tc]);
            pa[1] = __float_as_uint(QP[qr + tr + 8][k0 + tc]);
            pa[2] = __float_as_uint(QP[qr + tr][k0 + 4 + tc]);
            pa[3] = __float_as_uint(QP[qr + tr + 8][k0 + 4 + tc]);
            #pragma unroll
            for (int nf = 0; nf < 8; nf++) {
                uint32_t vb[2];
                vb[0] = __float_as_uint(Vs[k0 + tc][nf * 8 + tr]);
                vb[1] = __float_as_uint(Vs[k0 + 4 + tc][nf * 8 + tr]);
                MMA_TF32(oacc[nf], pa, vb);
            }
        }
        __syncthreads();
    }

    float i0 = 1.f / l0, i1 = 1.f / l1;
    size_t r0 = (qrow0 + qr + tr) * EMB + h * 64;
    size_t r1 = (qrow0 + qr + tr + 8) * EMB + h * 64;
    #pragma unroll
    for (int nf = 0; nf < 8; nf++) {
        int col = nf * 8 + tc * 2;
        *(float2*)(O + r0 + col) = make_float2(rnd_tf32(oacc[nf][0] * i0),
                                               rnd_tf32(oacc[nf][1] * i0));
        *(float2*)(O + r1 + col) = make_float2(rnd_tf32(oacc[nf][2] * i1),
                                               rnd_tf32(oacc[nf][3] * i1));
    }
}

// ---------------- launch ----------------------------------------------------
extern "C" void kernel_launch(void* const* d_in, const int* in_sizes, int n_in,
                              void* d_out, int out_size)
{
    const float* x     = (const float*)d_in[0];
    const float* Wq    = (const float*)d_in[1];
    const float* bq    = (const float*)d_in[2];
    const float* Wk    = (const float*)d_in[3];
    const float* bk    = (const float*)d_in[4];
    const float* Wv    = (const float*)d_in[5];
    const float* bv    = (const float*)d_in[6];
    const float* Wo    = (const float*)d_in[7];
    const float* bo    = (const float*)d_in[8];
    const float* W1    = (const float*)d_in[9];
    const float* b1    = (const float*)d_in[10];
    const float* W2    = (const float*)d_in[11];
    const float* b2    = (const float*)d_in[12];
    const float* ln1_g = (const float*)d_in[13];
    const float* ln1_b = (const float*)d_in[14];
    const float* ln2_g = (const float*)d_in[15];
    const float* ln2_b = (const float*)d_in[16];

    float *ln1, *q, *k, *v, *attn, *x1, *ln2, *ff;
    float *WqT, *WkT, *WvT, *WoT, *W1T, *W2T;
    cudaGetSymbolAddress((void**)&ln1,  g_ln1);
    cudaGetSymbolAddress((void**)&q,    g_q);
    cudaGetSymbolAddress((void**)&k,    g_k);
    cudaGetSymbolAddress((void**)&v,    g_v);
    cudaGetSymbolAddress((void**)&attn, g_attn);
    cudaGetSymbolAddress((void**)&x1,   g_x1);
    cudaGetSymbolAddress((void**)&ln2,  g_ln2);
    cudaGetSymbolAddress((void**)&ff,   g_ff);
    cudaGetSymbolAddress((void**)&WqT,  g_WqT);
    cudaGetSymbolAddress((void**)&WkT,  g_WkT);
    cudaGetSymbolAddress((void**)&WvT,  g_WvT);
    cudaGetSymbolAddress((void**)&WoT,  g_WoT);
    cudaGetSymbolAddress((void**)&W1T,  g_W1T);
    cudaGetSymbolAddress((void**)&W2T,  g_W2T);

    cudaFuncSetAttribute(gemm_mma<0>, cudaFuncAttributeMaxDynamicSharedMemorySize, GSMEM_BYTES);
    cudaFuncSetAttribute(gemm_mma<1>, cudaFuncAttributeMaxDynamicSharedMemorySize, GSMEM_BYTES);
    cudaFuncSetAttribute(gemm_mma<2>, cudaFuncAttributeMaxDynamicSharedMemorySize, GSMEM_BYTES);

    dim3 tb(32, 8);
    transpose_rnd<<<dim3(EMB / 32, EMB / 32), tb>>>(Wq, WqT, EMB, EMB);
    transpose_rnd<<<dim3(EMB / 32, EMB / 32), tb>>>(Wk, WkT, EMB, EMB);
    transpose_rnd<<<dim3(EMB / 32, EMB / 32), tb>>>(Wv, WvT, EMB, EMB);
    transpose_rnd<<<dim3(EMB / 32, EMB / 32), tb>>>(Wo, WoT, EMB, EMB);
    transpose_rnd<<<dim3(FFD / 32, EMB / 32), tb>>>(W1, W1T, EMB, FFD);
    transpose_rnd<<<dim3(EMB / 32, FFD / 32), tb>>>(W2, W2T, FFD, EMB);

    dim3 gEE(EMB / 128, NTOK / 128);
    dim3 gEF(FFD / 128, NTOK / 128);

    ln_kernel<<<NTOK, 256>>>(x, ln1_g, ln1_b, ln1);
    gemm_mma<0><<<gEE, 256, GSMEM_BYTES>>>(ln1, WqT, bq, nullptr, q, NTOK, EMB, EMB);
    gemm_mma<0><<<gEE, 256, GSMEM_BYTES>>>(ln1, WkT, bk, nullptr, k, NTOK, EMB, EMB);
    gemm_mma<0><<<gEE, 256, GSMEM_BYTES>>>(ln1, WvT, bv, nullptr, v, NTOK, EMB, EMB);
    attn_mma<<<dim3(SEQ / 64, 16, 2), 128>>>(q, k, v, attn);
    gemm_mma<2><<<gEE, 256, GSMEM_BYTES>>>(attn, WoT, bo, x, x1, NTOK, EMB, EMB);
    ln_kernel<<<NTOK, 256>>>(x1, ln2_g, ln2_b, ln2);
    gemm_mma<1><<<gEF, 256, GSMEM_BYTES>>>(ln2, W1T, b1, nullptr, ff, NTOK, FFD, EMB);
    gemm_mma<2><<<gEE, 256, GSMEM_BYTES>>>(ff, W2T, b2, x1, (float*)d_out, NTOK, EMB, FFD);
}